// round 2
// baseline (speedup 1.0000x reference)
#include <cuda_runtime.h>
#include <cstdint>

#define N_ROWS   131072
#define DIM      64
#define K_CODES  1024
#define KC       128          // codes per smem chunk
#define SE_STRIDE 68          // floats per code row in smem (16B-aligned, reduces STS conflicts)
#define THREADS  256

__device__ float g_csum[K_CODES];

// packed fp32x2 helpers (Blackwell FFMA2 path — only reachable via PTX)
__device__ __forceinline__ unsigned long long pack2(float lo, float hi) {
    unsigned long long r;
    asm("mov.b64 %0, {%1, %2};" : "=l"(r) : "f"(lo), "f"(hi));
    return r;
}
__device__ __forceinline__ float sum2(unsigned long long v) {
    float lo, hi;
    asm("mov.b64 {%0, %1}, %2;" : "=f"(lo), "=f"(hi) : "l"(v));
    return lo + hi;
}
#define FMA2(d, a, b, c) \
    asm("fma.rn.f32x2 %0, %1, %2, %3;" : "=l"(d) : "l"(a), "l"(b), "l"(c))

// ---------------------------------------------------------------------------
// Kernel 1: c[k] = 0.5 * sum_d emb[d][k]^2
// ---------------------------------------------------------------------------
__global__ void vq_csum_kernel(const float* __restrict__ emb) {
    int k = blockIdx.x * blockDim.x + threadIdx.x;
    if (k < K_CODES) {
        float s = 0.0f;
#pragma unroll
        for (int d = 0; d < DIM; d++) {
            float v = emb[d * K_CODES + k];
            s = fmaf(v, v, s);
        }
        g_csum[k] = 0.5f * s;
    }
}

// ---------------------------------------------------------------------------
// Kernel 2: per-row argmin over K + gather
// dist_k = 0.5*||e_k||^2 - f . e_k   (monotonic in true distance)
// ---------------------------------------------------------------------------
__global__ __launch_bounds__(THREADS, 2)
void vq_main_kernel(const float* __restrict__ x,
                    const float* __restrict__ emb,
                    float* __restrict__ out) {
    __shared__ __align__(16) float se[KC * SE_STRIDE];
    __shared__ float sc[KC];

    const int row = blockIdx.x * THREADS + threadIdx.x;

    // Load this thread's row and pack into 32 f32x2 registers.
    unsigned long long f2[DIM / 2];
    {
        const float4* xr = reinterpret_cast<const float4*>(x + (size_t)row * DIM);
#pragma unroll
        for (int i = 0; i < DIM / 4; i++) {
            float4 v = xr[i];
            f2[2 * i]     = pack2(v.x, v.y);
            f2[2 * i + 1] = pack2(v.z, v.w);
        }
    }

    float minv = 3.0e38f;
    int   mink = 0;

    for (int k0 = 0; k0 < K_CODES; k0 += KC) {
        __syncthreads();
        // Stage E chunk transposed: se[kk][d] = emb[d][k0+kk].
        // Global reads coalesced (kk contiguous); STS conflicts amortized.
#pragma unroll
        for (int t = 0; t < (KC * DIM) / THREADS; t++) {
            int i  = threadIdx.x + t * THREADS;
            int kk = i & (KC - 1);
            int d  = i >> 7;           // i / KC  (KC == 128)
            se[kk * SE_STRIDE + d] = emb[d * K_CODES + k0 + kk];
        }
        if (threadIdx.x < KC)
            sc[threadIdx.x] = g_csum[k0 + threadIdx.x];
        __syncthreads();

        // 4 codes at a time: 4 independent FFMA2 accumulator chains.
        for (int kk = 0; kk < KC; kk += 4) {
            unsigned long long a0 = 0ull, a1 = 0ull, a2 = 0ull, a3 = 0ull;
            const float* p0 = &se[(kk + 0) * SE_STRIDE];
            const float* p1 = &se[(kk + 1) * SE_STRIDE];
            const float* p2 = &se[(kk + 2) * SE_STRIDE];
            const float* p3 = &se[(kk + 3) * SE_STRIDE];
#pragma unroll
            for (int i = 0; i < DIM / 4; i++) {
                // uniform-address broadcast LDS.128 (conflict-free)
                ulonglong2 e0 = *reinterpret_cast<const ulonglong2*>(p0 + 4 * i);
                ulonglong2 e1 = *reinterpret_cast<const ulonglong2*>(p1 + 4 * i);
                ulonglong2 e2 = *reinterpret_cast<const ulonglong2*>(p2 + 4 * i);
                ulonglong2 e3 = *reinterpret_cast<const ulonglong2*>(p3 + 4 * i);
                FMA2(a0, f2[2 * i], e0.x, a0);
                FMA2(a1, f2[2 * i], e1.x, a1);
                FMA2(a2, f2[2 * i], e2.x, a2);
                FMA2(a3, f2[2 * i], e3.x, a3);
                FMA2(a0, f2[2 * i + 1], e0.y, a0);
                FMA2(a1, f2[2 * i + 1], e1.y, a1);
                FMA2(a2, f2[2 * i + 1], e2.y, a2);
                FMA2(a3, f2[2 * i + 1], e3.y, a3);
            }
            float d0 = sc[kk + 0] - sum2(a0);
            float d1 = sc[kk + 1] - sum2(a1);
            float d2 = sc[kk + 2] - sum2(a2);
            float d3 = sc[kk + 3] - sum2(a3);
            // sequential strict-< keeps first occurrence (matches jnp.argmin)
            if (d0 < minv) { minv = d0; mink = k0 + kk + 0; }
            if (d1 < minv) { minv = d1; mink = k0 + kk + 1; }
            if (d2 < minv) { minv = d2; mink = k0 + kk + 2; }
            if (d3 < minv) { minv = d3; mink = k0 + kk + 3; }
        }
    }

    // Gather codebook column mink (E is L2-resident) and store the row.
    const float* ec = emb + mink;
    float4* op = reinterpret_cast<float4*>(out + (size_t)row * DIM);
#pragma unroll
    for (int i = 0; i < DIM / 4; i++) {
        float4 v;
        v.x = ec[(4 * i + 0) * K_CODES];
        v.y = ec[(4 * i + 1) * K_CODES];
        v.z = ec[(4 * i + 2) * K_CODES];
        v.w = ec[(4 * i + 3) * K_CODES];
        op[i] = v;
    }
}

extern "C" void kernel_launch(void* const* d_in, const int* in_sizes, int n_in,
                              void* d_out, int out_size) {
    const float* x   = (const float*)d_in[0];   // [128*1024, 64]
    const float* emb = (const float*)d_in[1];   // [64, 1024]
    float* out = (float*)d_out;

    vq_csum_kernel<<<(K_CODES + 255) / 256, 256>>>(emb);
    vq_main_kernel<<<N_ROWS / THREADS, THREADS>>>(x, emb, out);
}

// round 3
// speedup vs baseline: 1.2888x; 1.2888x over previous
#include <cuda_runtime.h>
#include <cstdint>

#define N_ROWS   131072
#define DIM      64
#define K_CODES  1024
#define KC       128          // codes per smem chunk
#define SE_STRIDE 68          // floats per code row in smem (16B-aligned rows)
#define THREADS  128
#define RPT      2            // rows per thread

__device__ float g_csum[K_CODES];

__device__ __forceinline__ unsigned long long pack2(float lo, float hi) {
    unsigned long long r;
    asm("mov.b64 %0, {%1, %2};" : "=l"(r) : "f"(lo), "f"(hi));
    return r;
}
__device__ __forceinline__ float sum2(unsigned long long v) {
    float lo, hi;
    asm("mov.b64 {%0, %1}, %2;" : "=f"(lo), "=f"(hi) : "l"(v));
    return lo + hi;
}
#define FMA2(d, a, b, c) \
    asm("fma.rn.f32x2 %0, %1, %2, %3;" : "=l"(d) : "l"(a), "l"(b), "l"(c))

// ---------------------------------------------------------------------------
// Kernel 1: c[k] = 0.5 * sum_d emb[d][k]^2
// ---------------------------------------------------------------------------
__global__ void vq_csum_kernel(const float* __restrict__ emb) {
    int k = blockIdx.x * blockDim.x + threadIdx.x;
    if (k < K_CODES) {
        float s = 0.0f;
#pragma unroll
        for (int d = 0; d < DIM; d++) {
            float v = emb[d * K_CODES + k];
            s = fmaf(v, v, s);
        }
        g_csum[k] = 0.5f * s;
    }
}

// ---------------------------------------------------------------------------
// Kernel 2: 2 rows per thread. dist_k = 0.5*||e_k||^2 - f.e_k
// Each staged E value in smem now feeds 2x the FMAs -> L1 pressure halved.
// ---------------------------------------------------------------------------
__global__ __launch_bounds__(THREADS, 2)
void vq_main_kernel(const float* __restrict__ x,
                    const float* __restrict__ emb,
                    float* __restrict__ out) {
    __shared__ __align__(16) float se[KC * SE_STRIDE];
    __shared__ float sc[KC];

    // Block handles THREADS*RPT consecutive rows; thread t owns rows
    // base + t and base + t + THREADS (both coalesced on load/store).
    const int base = blockIdx.x * THREADS * RPT;
    const int r0   = base + threadIdx.x;
    const int r1   = base + threadIdx.x + THREADS;

    unsigned long long fA[DIM / 2];   // row 0 packed as f32x2
    unsigned long long fB[DIM / 2];   // row 1 packed as f32x2
    {
        const float4* xa = reinterpret_cast<const float4*>(x + (size_t)r0 * DIM);
        const float4* xb = reinterpret_cast<const float4*>(x + (size_t)r1 * DIM);
#pragma unroll
        for (int i = 0; i < DIM / 4; i++) {
            float4 va = xa[i];
            float4 vb = xb[i];
            fA[2 * i]     = pack2(va.x, va.y);
            fA[2 * i + 1] = pack2(va.z, va.w);
            fB[2 * i]     = pack2(vb.x, vb.y);
            fB[2 * i + 1] = pack2(vb.z, vb.w);
        }
    }

    float minvA = 3.0e38f, minvB = 3.0e38f;
    int   minkA = 0,       minkB = 0;

    for (int k0 = 0; k0 < K_CODES; k0 += KC) {
        __syncthreads();
        // Stage E chunk transposed: se[kk][d] = emb[d][k0+kk].
        // THREADS=128 -> kk == threadIdx.x, d == t: global reads coalesced.
#pragma unroll
        for (int t = 0; t < DIM; t++) {
            se[threadIdx.x * SE_STRIDE + t] = emb[t * K_CODES + k0 + threadIdx.x];
        }
        sc[threadIdx.x] = g_csum[k0 + threadIdx.x];
        __syncthreads();

        // 4 codes x 2 rows = 8 independent FFMA2 chains.
        for (int kk = 0; kk < KC; kk += 4) {
            unsigned long long a0 = 0ull, a1 = 0ull, a2 = 0ull, a3 = 0ull;
            unsigned long long b0 = 0ull, b1 = 0ull, b2 = 0ull, b3 = 0ull;
            const float* p0 = &se[(kk + 0) * SE_STRIDE];
            const float* p1 = &se[(kk + 1) * SE_STRIDE];
            const float* p2 = &se[(kk + 2) * SE_STRIDE];
            const float* p3 = &se[(kk + 3) * SE_STRIDE];
#pragma unroll
            for (int i = 0; i < DIM / 4; i++) {
                // uniform-address broadcast LDS.128 (conflict-free)
                ulonglong2 e0 = *reinterpret_cast<const ulonglong2*>(p0 + 4 * i);
                ulonglong2 e1 = *reinterpret_cast<const ulonglong2*>(p1 + 4 * i);
                ulonglong2 e2 = *reinterpret_cast<const ulonglong2*>(p2 + 4 * i);
                ulonglong2 e3 = *reinterpret_cast<const ulonglong2*>(p3 + 4 * i);
                unsigned long long u0 = fA[2 * i], u1 = fA[2 * i + 1];
                unsigned long long w0 = fB[2 * i], w1 = fB[2 * i + 1];
                FMA2(a0, u0, e0.x, a0);
                FMA2(a1, u0, e1.x, a1);
                FMA2(a2, u0, e2.x, a2);
                FMA2(a3, u0, e3.x, a3);
                FMA2(b0, w0, e0.x, b0);
                FMA2(b1, w0, e1.x, b1);
                FMA2(b2, w0, e2.x, b2);
                FMA2(b3, w0, e3.x, b3);
                FMA2(a0, u1, e0.y, a0);
                FMA2(a1, u1, e1.y, a1);
                FMA2(a2, u1, e2.y, a2);
                FMA2(a3, u1, e3.y, a3);
                FMA2(b0, w1, e0.y, b0);
                FMA2(b1, w1, e1.y, b1);
                FMA2(b2, w1, e2.y, b2);
                FMA2(b3, w1, e3.y, b3);
            }
            float c0 = sc[kk + 0], c1 = sc[kk + 1], c2 = sc[kk + 2], c3 = sc[kk + 3];
            float dA0 = c0 - sum2(a0), dA1 = c1 - sum2(a1);
            float dA2 = c2 - sum2(a2), dA3 = c3 - sum2(a3);
            float dB0 = c0 - sum2(b0), dB1 = c1 - sum2(b1);
            float dB2 = c2 - sum2(b2), dB3 = c3 - sum2(b3);
            // sequential strict-< keeps first occurrence (matches jnp.argmin)
            if (dA0 < minvA) { minvA = dA0; minkA = k0 + kk + 0; }
            if (dA1 < minvA) { minvA = dA1; minkA = k0 + kk + 1; }
            if (dA2 < minvA) { minvA = dA2; minkA = k0 + kk + 2; }
            if (dA3 < minvA) { minvA = dA3; minkA = k0 + kk + 3; }
            if (dB0 < minvB) { minvB = dB0; minkB = k0 + kk + 0; }
            if (dB1 < minvB) { minvB = dB1; minkB = k0 + kk + 1; }
            if (dB2 < minvB) { minvB = dB2; minkB = k0 + kk + 2; }
            if (dB3 < minvB) { minvB = dB3; minkB = k0 + kk + 3; }
        }
    }

    // Gather codebook columns (E is L2-resident), store both rows coalesced.
    {
        const float* ec = emb + minkA;
        float4* op = reinterpret_cast<float4*>(out + (size_t)r0 * DIM);
#pragma unroll
        for (int i = 0; i < DIM / 4; i++) {
            float4 v;
            v.x = ec[(4 * i + 0) * K_CODES];
            v.y = ec[(4 * i + 1) * K_CODES];
            v.z = ec[(4 * i + 2) * K_CODES];
            v.w = ec[(4 * i + 3) * K_CODES];
            op[i] = v;
        }
    }
    {
        const float* ec = emb + minkB;
        float4* op = reinterpret_cast<float4*>(out + (size_t)r1 * DIM);
#pragma unroll
        for (int i = 0; i < DIM / 4; i++) {
            float4 v;
            v.x = ec[(4 * i + 0) * K_CODES];
            v.y = ec[(4 * i + 1) * K_CODES];
            v.z = ec[(4 * i + 2) * K_CODES];
            v.w = ec[(4 * i + 3) * K_CODES];
            op[i] = v;
        }
    }
}

extern "C" void kernel_launch(void* const* d_in, const int* in_sizes, int n_in,
                              void* d_out, int out_size) {
    const float* x   = (const float*)d_in[0];   // [131072, 64]
    const float* emb = (const float*)d_in[1];   // [64, 1024]
    float* out = (float*)d_out;

    vq_csum_kernel<<<(K_CODES + 255) / 256, 256>>>(emb);
    vq_main_kernel<<<N_ROWS / (THREADS * RPT), THREADS>>>(x, emb, out);
}